// round 15
// baseline (speedup 1.0000x reference)
#include <cuda_runtime.h>
#include <cuda_fp16.h>
#include <math.h>
#include <stdint.h>

#define TOK    1568
#define BATCH  4
#define CDIM   768
#define TTOK   (BATCH*TOK)
#define QKVDIM 2304
#define HID    3072
#define NHEAD  12
#define DHEAD  64

#define W_QKV  0
#define W_PROJ 1769472
#define W_FC1  2359296
#define W_FC2  4718592
#define W_TOT  7077888

__device__ float  g_t[TTOK * CDIM];
__device__ __half g_q16[TTOK * QKVDIM];
__device__ __half g_h16[TTOK * CDIM];
__device__ __half g_o16[TTOK * CDIM];
__device__ __half g_m16[TTOK * HID];
__device__ __half g_w16[W_TOT];

// ---------------- ptx helpers ----------------
__device__ __forceinline__ void mma_f16(float* d, const uint32_t* a, const uint32_t* b) {
    asm volatile(
        "mma.sync.aligned.m16n8k16.row.col.f32.f16.f16.f32 "
        "{%0,%1,%2,%3}, {%4,%5,%6,%7}, {%8,%9}, {%0,%1,%2,%3};"
        : "+f"(d[0]), "+f"(d[1]), "+f"(d[2]), "+f"(d[3])
        : "r"(a[0]), "r"(a[1]), "r"(a[2]), "r"(a[3]), "r"(b[0]), "r"(b[1]));
}
__device__ __forceinline__ void ldsm4(uint32_t* r, uint32_t addr) {
    asm volatile("ldmatrix.sync.aligned.m8n8.x4.shared.b16 {%0,%1,%2,%3}, [%4];"
                 : "=r"(r[0]), "=r"(r[1]), "=r"(r[2]), "=r"(r[3]) : "r"(addr));
}
__device__ __forceinline__ void ldsm4t(uint32_t* r, uint32_t addr) {
    asm volatile("ldmatrix.sync.aligned.m8n8.x4.trans.shared.b16 {%0,%1,%2,%3}, [%4];"
                 : "=r"(r[0]), "=r"(r[1]), "=r"(r[2]), "=r"(r[3]) : "r"(addr));
}
__device__ __forceinline__ void cp16(uint32_t dst, const void* src) {
    asm volatile("cp.async.cg.shared.global [%0], [%1], 16;" :: "r"(dst), "l"(src));
}
__device__ __forceinline__ void cp_commit() { asm volatile("cp.async.commit_group;"); }
template <int N> __device__ __forceinline__ void cp_wait() {
    asm volatile("cp.async.wait_group %0;" :: "n"(N));
}
__device__ __forceinline__ float gelu_exact(float v) {
    return 0.5f * v * (1.f + erff(v * 0.70710678118654752f));
}

// ---------------- fused fp32 -> fp16 weight convert ----------------
__global__ void cvtw(const float* __restrict__ qkv_w, const float* __restrict__ proj_w,
                     const float* __restrict__ fc1_w, const float* __restrict__ fc2_w,
                     __half* __restrict__ dst) {
    int i = blockIdx.x * 256 + threadIdx.x;
    float v;
    if (i < W_PROJ)      v = qkv_w[i];
    else if (i < W_FC1)  v = proj_w[i - W_PROJ];
    else if (i < W_FC2)  v = fc1_w[i - W_FC1];
    else                 v = fc2_w[i - W_FC2];
    dst[i] = __float2half(v);
}

// ---------------- conv + bias + residual + tokenize ----------------
__global__ void conv_pos_kernel(const float* __restrict__ x,
                                const float* __restrict__ pw,
                                const float* __restrict__ pb) {
    int bc = blockIdx.x;
    int c  = bc % CDIM;
    int b  = bc / CDIM;
    __shared__ float sx[TOK];
    __shared__ float sw[27];
    int tid = threadIdx.x;
    const float* xs = x + (size_t)bc * TOK;
    for (int i = tid; i < TOK; i += 256) sx[i] = xs[i];
    if (tid < 27) sw[tid] = pw[c * 27 + tid];
    __syncthreads();
    float pbv = pb[c];
    for (int idx = tid; idx < TOK; idx += 256) {
        int d = idx / 196; int r = idx - d * 196;
        int h = r / 14;    int w = r - h * 14;
        float acc = 0.f;
        #pragma unroll
        for (int kd = 0; kd < 3; kd++) {
            int dd = d + kd - 1;
            if (dd < 0 || dd >= 8) continue;
            #pragma unroll
            for (int kh = 0; kh < 3; kh++) {
                int hh = h + kh - 1;
                if (hh < 0 || hh >= 14) continue;
                #pragma unroll
                for (int kw = 0; kw < 3; kw++) {
                    int ww = w + kw - 1;
                    if (ww < 0 || ww >= 14) continue;
                    acc += sw[kd * 9 + kh * 3 + kw] * sx[dd * 196 + hh * 14 + ww];
                }
            }
        }
        g_t[(size_t)(b * TOK + idx) * CDIM + c] = sx[idx] + acc + pbv;
    }
}

// ---------------- LayerNorm -> fp16 ----------------
__global__ void ln_kernel(const float* __restrict__ in, const float* __restrict__ w,
                          const float* __restrict__ bsrc, __half* __restrict__ out) {
    int t = blockIdx.x;
    int tid = threadIdx.x;
    const float* row = in + (size_t)t * CDIM;
    float v0 = row[tid], v1 = row[tid + 256], v2 = row[tid + 512];
    float s  = v0 + v1 + v2;
    float sq = v0 * v0 + v1 * v1 + v2 * v2;
    #pragma unroll
    for (int off = 16; off; off >>= 1) {
        s  += __shfl_xor_sync(0xffffffffu, s,  off);
        sq += __shfl_xor_sync(0xffffffffu, sq, off);
    }
    __shared__ float ss[8], ssq[8];
    int wid = tid >> 5, lid = tid & 31;
    if (lid == 0) { ss[wid] = s; ssq[wid] = sq; }
    __syncthreads();
    if (tid < 32) {
        s  = (lid < 8) ? ss[lid]  : 0.f;
        sq = (lid < 8) ? ssq[lid] : 0.f;
        #pragma unroll
        for (int off = 4; off; off >>= 1) {
            s  += __shfl_xor_sync(0xffffffffu, s,  off);
            sq += __shfl_xor_sync(0xffffffffu, sq, off);
        }
        if (lid == 0) { ss[0] = s; ssq[0] = sq; }
    }
    __syncthreads();
    float mean = ss[0] * (1.f / CDIM);
    float var  = ssq[0] * (1.f / CDIM) - mean * mean;
    float rs   = rsqrtf(var + 1e-5f);
    __half* orow = out + (size_t)t * CDIM;
    orow[tid]       = __float2half((v0 - mean) * rs * w[tid]       + bsrc[tid]);
    orow[tid + 256] = __float2half((v1 - mean) * rs * w[tid + 256] + bsrc[tid + 256]);
    orow[tid + 512] = __float2half((v2 - mean) * rs * w[tid + 512] + bsrc[tid + 512]);
}

// ---------------- fp16 mma GEMM: BK=64, 3-stage cp.async, 1 barrier per 64-K ----------------
// Rows: 64 halves + 8 pad = 72 halves (144 B, word-banks 4r%32 conflict-free — attn layout).
// MODE 1: Cf=acc+bias+resid ; 2: Ch=gelu(acc+bias) ; 3: Ch=acc
#define GB_STRIDEH 72
#define GB_MATH    (128 * GB_STRIDEH)        // halves per matrix per stage
#define GB_STAGEB  (2 * GB_MATH * 2)         // 36864 bytes
#define GBSMEM_B   (3 * GB_STAGEB)           // 110592 bytes

template <int MODE>
__global__ void __launch_bounds__(256, 2)
gemm_h(const __half* __restrict__ A, const __half* __restrict__ B,
       const float* __restrict__ bias, const float* __restrict__ resid,
       float* __restrict__ Cf, __half* __restrict__ Ch, int N, int K) {
    extern __shared__ __align__(16) __half smh[];
    int tid = threadIdx.x;
    int lane = tid & 31, warp = tid >> 5;
    int wm = warp >> 2, wn = warp & 3;
    int m0 = blockIdx.y << 7, n0 = blockIdx.x << 7;
    uint32_t smbase = (uint32_t)__cvta_generic_to_shared(smh);

    // loader: row = tid>>1 (0..127), half-row = tid&1 (32 halves = 4 granules)
    int lrow = tid >> 1;
    int lhalf = tid & 1;
    const __half* Ag = A + (size_t)(m0 + lrow) * K + lhalf * 32;
    const __half* Bg = B + (size_t)(n0 + lrow) * K + lhalf * 32;
    uint32_t sa0 = smbase + (lrow * GB_STRIDEH + lhalf * 32) * 2;
    uint32_t sb0 = sa0 + GB_MATH * 2;

    int nch = K >> 6;
    auto load_chunk = [&](int ch) {
        uint32_t d = (uint32_t)(ch % 3) * GB_STAGEB;
        int off = ch << 6;
        #pragma unroll
        for (int g = 0; g < 4; g++) {
            cp16(sa0 + d + g * 16, Ag + off + g * 8);
            cp16(sb0 + d + g * 16, Bg + off + g * 8);
        }
        cp_commit();
    };

    float acc[4][4][4];
    #pragma unroll
    for (int mi = 0; mi < 4; mi++)
        #pragma unroll
        for (int ni = 0; ni < 4; ni++)
            #pragma unroll
            for (int r = 0; r < 4; r++) acc[mi][ni][r] = 0.f;

    int grp = lane >> 3, trow = lane & 7;
    int arow = ((grp & 1) << 3) + trow, acol = (grp >> 1) << 3;
    int brow = ((grp >> 1) << 3) + trow, bcol = (grp & 1) << 3;
    uint32_t aaddr[4], baddr[2];
    #pragma unroll
    for (int mi = 0; mi < 4; mi++)
        aaddr[mi] = smbase + ((wm * 64 + mi * 16 + arow) * GB_STRIDEH + acol) * 2;
    #pragma unroll
    for (int np = 0; np < 2; np++)
        baddr[np] = smbase + GB_MATH * 2 + ((wn * 32 + np * 16 + brow) * GB_STRIDEH + bcol) * 2;

    load_chunk(0);
    load_chunk(1);
    for (int ch = 0; ch < nch; ch++) {
        if (ch < nch - 1) cp_wait<1>(); else cp_wait<0>();
        __syncthreads();
        if (ch + 2 < nch) load_chunk(ch + 2);   // buffer (ch+2)%3 freed by this barrier
        uint32_t soff = (uint32_t)(ch % 3) * GB_STAGEB;
        #pragma unroll
        for (int kt = 0; kt < 4; kt++) {
            uint32_t koff = soff + kt * 32;
            uint32_t af[4][4], bfr[2][4];
            #pragma unroll
            for (int mi = 0; mi < 4; mi++) ldsm4(af[mi], aaddr[mi] + koff);
            #pragma unroll
            for (int np = 0; np < 2; np++) ldsm4(bfr[np], baddr[np] + koff);
            #pragma unroll
            for (int mi = 0; mi < 4; mi++)
                #pragma unroll
                for (int ni = 0; ni < 4; ni++)
                    mma_f16(acc[mi][ni], af[mi], &bfr[ni >> 1][(ni & 1) * 2]);
        }
    }

    int r0 = lane >> 2, cq = (lane & 3) * 2;
    #pragma unroll
    for (int mi = 0; mi < 4; mi++) {
        int rowA = m0 + wm * 64 + mi * 16 + r0;
        int rowB = rowA + 8;
        #pragma unroll
        for (int ni = 0; ni < 4; ni++) {
            int col = n0 + wn * 32 + ni * 8 + cq;
            float2 va = make_float2(acc[mi][ni][0], acc[mi][ni][1]);
            float2 vb = make_float2(acc[mi][ni][2], acc[mi][ni][3]);
            if (MODE == 1) {
                float2 bv = *(const float2*)(bias + col);
                float2 ra = *(const float2*)(resid + (size_t)rowA * N + col);
                float2 rb = *(const float2*)(resid + (size_t)rowB * N + col);
                va.x += bv.x + ra.x; va.y += bv.y + ra.y;
                vb.x += bv.x + rb.x; vb.y += bv.y + rb.y;
                *(float2*)(Cf + (size_t)rowA * N + col) = va;
                *(float2*)(Cf + (size_t)rowB * N + col) = vb;
            } else if (MODE == 2) {
                float2 bv = *(const float2*)(bias + col);
                va.x = gelu_exact(va.x + bv.x); va.y = gelu_exact(va.y + bv.y);
                vb.x = gelu_exact(vb.x + bv.x); vb.y = gelu_exact(vb.y + bv.y);
                *(__half2*)(Ch + (size_t)rowA * N + col) = __floats2half2_rn(va.x, va.y);
                *(__half2*)(Ch + (size_t)rowB * N + col) = __floats2half2_rn(vb.x, vb.y);
            } else {
                *(__half2*)(Ch + (size_t)rowA * N + col) = __floats2half2_rn(va.x, va.y);
                *(__half2*)(Ch + (size_t)rowB * N + col) = __floats2half2_rn(vb.x, vb.y);
            }
        }
    }
}

// ---------------- fp16 flash attention (R13 winner, unchanged) ----------------
__global__ void __launch_bounds__(128)
attn_h(const __half* __restrict__ qkv, __half* __restrict__ o) {
    __shared__ __align__(16) __half Ks[2][64 * 72];
    __shared__ __align__(16) __half Vs[2][64 * 72];
    __shared__ __align__(16) __half Ps[64 * 72];
    int tid = threadIdx.x, lane = tid & 31, warp = tid >> 5;
    int bh = blockIdx.y;
    int b = bh / NHEAD, h = bh % NHEAD;
    int q0 = blockIdx.x * 64;
    const __half* base = qkv + (size_t)b * TOK * QKVDIM + h * DHEAD;

    int r0 = lane >> 2, kq = lane & 3;
    int qa = q0 + warp * 16 + r0;
    int qb = qa + 8;
    bool va = qa < TOK, vb = qb < TOK;

    uint32_t qf[4][4];
    {
        const __half2 sc = __floats2half2_rn(0.125f, 0.125f);
        const __half* pa = base + (size_t)qa * QKVDIM;
        const __half* pb = base + (size_t)qb * QKVDIM;
        #pragma unroll
        for (int kt = 0; kt < 4; kt++) {
            int k = kt * 16 + 2 * kq;
            __half2 v;
            v = va ? __hmul2(*(const __half2*)(pa + k), sc) : __floats2half2_rn(0.f, 0.f);
            qf[kt][0] = *(uint32_t*)&v;
            v = vb ? __hmul2(*(const __half2*)(pb + k), sc) : __floats2half2_rn(0.f, 0.f);
            qf[kt][1] = *(uint32_t*)&v;
            v = va ? __hmul2(*(const __half2*)(pa + k + 8), sc) : __floats2half2_rn(0.f, 0.f);
            qf[kt][2] = *(uint32_t*)&v;
            v = vb ? __hmul2(*(const __half2*)(pb + k + 8), sc) : __floats2half2_rn(0.f, 0.f);
            qf[kt][3] = *(uint32_t*)&v;
        }
    }

    uint32_t ksm = (uint32_t)__cvta_generic_to_shared(Ks);
    uint32_t vsm = (uint32_t)__cvta_generic_to_shared(Vs);
    uint32_t psm = (uint32_t)__cvta_generic_to_shared(Ps);
    const uint32_t KVBUF = 64 * 72 * 2;

    int ldrow = tid >> 3, ldc8 = (tid & 7) << 3;
    auto loadKV = [&](int kc, int st) {
        uint32_t kb = ksm + st * KVBUF;
        uint32_t vbuf = vsm + st * KVBUF;
        #pragma unroll
        for (int i = 0; i < 4; i++) {
            int row = ldrow + i * 16;
            int kg = kc * 64 + row;
            if (kg > TOK - 1) kg = TOK - 1;
            const __half* src = base + (size_t)kg * QKVDIM;
            uint32_t doff = (row * 72 + ldc8) * 2;
            cp16(kb + doff,   src + CDIM + ldc8);
            cp16(vbuf + doff, src + 2 * CDIM + ldc8);
        }
        cp_commit();
    };

    int grp = lane >> 3, trow = lane & 7;
    int arow = ((grp & 1) << 3) + trow, acol = (grp >> 1) << 3;
    int brow = ((grp >> 1) << 3) + trow, bcol = (grp & 1) << 3;
    int vrow = ((grp & 1) << 3) + trow,  vcol = (grp >> 1) << 3;
    uint32_t koff_[4], voff_[4], paddr;
    #pragma unroll
    for (int np = 0; np < 4; np++) {
        koff_[np] = ((np * 16 + brow) * 72 + bcol) * 2;
        voff_[np] = (vrow * 72 + np * 16 + vcol) * 2;
    }
    paddr = psm + ((warp * 16 + arow) * 72 + acol) * 2;

    float oacc[8][4];
    #pragma unroll
    for (int nt = 0; nt < 8; nt++)
        #pragma unroll
        for (int rr = 0; rr < 4; rr++) oacc[nt][rr] = 0.f;
    float mi0 = -1e30f, mi1 = -1e30f, li0 = 0.f, li1 = 0.f;
    int prow = warp * 16 + r0;

    loadKV(0, 0);
    for (int kc = 0; kc < 25; kc++) {
        cp_wait<0>();
        __syncthreads();
        if (kc + 1 < 25) loadKV(kc + 1, (kc + 1) & 1);
        uint32_t kb = ksm + (kc & 1) * KVBUF;
        uint32_t vbuf = vsm + (kc & 1) * KVBUF;

        float s[8][4];
        #pragma unroll
        for (int ni = 0; ni < 8; ni++)
            #pragma unroll
            for (int rr = 0; rr < 4; rr++) s[ni][rr] = 0.f;
        #pragma unroll
        for (int kt = 0; kt < 4; kt++) {
            uint32_t koff = kt * 32;
            #pragma unroll
            for (int np = 0; np < 4; np++) {
                uint32_t bb[4];
                ldsm4(bb, kb + koff_[np] + koff);
                mma_f16(s[2 * np],     qf[kt], bb);
                mma_f16(s[2 * np + 1], qf[kt], bb + 2);
            }
        }
        if (kc == 24) {
            #pragma unroll
            for (int ni = 0; ni < 8; ni++) {
                int c = kc * 64 + ni * 8 + kq * 2;
                if (c >= TOK)     { s[ni][0] = -1e30f; s[ni][2] = -1e30f; }
                if (c + 1 >= TOK) { s[ni][1] = -1e30f; s[ni][3] = -1e30f; }
            }
        }
        float mr0 = -1e30f, mr1 = -1e30f;
        #pragma unroll
        for (int ni = 0; ni < 8; ni++) {
            mr0 = fmaxf(mr0, fmaxf(s[ni][0], s[ni][1]));
            mr1 = fmaxf(mr1, fmaxf(s[ni][2], s[ni][3]));
        }
        mr0 = fmaxf(mr0, __shfl_xor_sync(0xffffffffu, mr0, 1));
        mr0 = fmaxf(mr0, __shfl_xor_sync(0xffffffffu, mr0, 2));
        mr1 = fmaxf(mr1, __shfl_xor_sync(0xffffffffu, mr1, 1));
        mr1 = fmaxf(mr1, __shfl_xor_sync(0xffffffffu, mr1, 2));
        float mn0 = fmaxf(mi0, mr0), mn1 = fmaxf(mi1, mr1);
        float a0 = __expf(mi0 - mn0), a1 = __expf(mi1 - mn1);
        float sum0 = 0.f, sum1 = 0.f;
        #pragma unroll
        for (int ni = 0; ni < 8; ni++) {
            s[ni][0] = __expf(s[ni][0] - mn0);
            s[ni][1] = __expf(s[ni][1] - mn0);
            s[ni][2] = __expf(s[ni][2] - mn1);
            s[ni][3] = __expf(s[ni][3] - mn1);
            sum0 += s[ni][0] + s[ni][1];
            sum1 += s[ni][2] + s[ni][3];
        }
        sum0 += __shfl_xor_sync(0xffffffffu, sum0, 1);
        sum0 += __shfl_xor_sync(0xffffffffu, sum0, 2);
        sum1 += __shfl_xor_sync(0xffffffffu, sum1, 1);
        sum1 += __shfl_xor_sync(0xffffffffu, sum1, 2);
        li0 = li0 * a0 + sum0; li1 = li1 * a1 + sum1;
        mi0 = mn0; mi1 = mn1;
        #pragma unroll
        for (int nt = 0; nt < 8; nt++) {
            oacc[nt][0] *= a0; oacc[nt][1] *= a0;
            oacc[nt][2] *= a1; oacc[nt][3] *= a1;
        }
        #pragma unroll
        for (int ni = 0; ni < 8; ni++) {
            int col = ni * 8 + kq * 2;
            *(__half2*)&Ps[prow * 72 + col]       = __floats2half2_rn(s[ni][0], s[ni][1]);
            *(__half2*)&Ps[(prow + 8) * 72 + col] = __floats2half2_rn(s[ni][2], s[ni][3]);
        }
        __syncwarp();
        #pragma unroll
        for (int kt = 0; kt < 4; kt++) {
            uint32_t pf[4];
            ldsm4(pf, paddr + kt * 32);
            uint32_t vko = kt * 16 * 72 * 2;
            #pragma unroll
            for (int np = 0; np < 4; np++) {
                uint32_t bb[4];
                ldsm4t(bb, vbuf + voff_[np] + vko);
                mma_f16(oacc[2 * np],     pf, bb);
                mma_f16(oacc[2 * np + 1], pf, bb + 2);
            }
        }
    }

    float inv0 = 1.f / li0, inv1 = 1.f / li1;
    #pragma unroll
    for (int nt = 0; nt < 8; nt++) {
        int col = h * DHEAD + nt * 8 + kq * 2;
        if (va)
            *(__half2*)(o + (size_t)(b * TOK + qa) * CDIM + col) =
                __floats2half2_rn(oacc[nt][0] * inv0, oacc[nt][1] * inv0);
        if (vb)
            *(__half2*)(o + (size_t)(b * TOK + qb) * CDIM + col) =
                __floats2half2_rn(oacc[nt][2] * inv1, oacc[nt][3] * inv1);
    }
}

// ---------------- untokenize ----------------
__global__ void untok_kernel(float* __restrict__ out) {
    __shared__ float tile[32][33];
    int b  = blockIdx.z;
    int s0 = blockIdx.x * 32;
    int c0 = blockIdx.y * 32;
    int tx = threadIdx.x, ty = threadIdx.y;
    #pragma unroll
    for (int r = ty; r < 32; r += 8)
        tile[r][tx] = g_t[(size_t)(b * TOK + s0 + r) * CDIM + c0 + tx];
    __syncthreads();
    #pragma unroll
    for (int r = ty; r < 32; r += 8)
        out[(size_t)(b * CDIM + c0 + r) * TOK + s0 + tx] = tile[tx][r];
}

// ---------------- launch ----------------
extern "C" void kernel_launch(void* const* d_in, const int* in_sizes, int n_in,
                              void* d_out, int out_size) {
    const float* x      = (const float*)d_in[0];
    const float* pos_w  = (const float*)d_in[1];
    const float* pos_b  = (const float*)d_in[2];
    const float* ln1_w  = (const float*)d_in[3];
    const float* ln1_b  = (const float*)d_in[4];
    const float* qkv_w  = (const float*)d_in[5];
    const float* proj_w = (const float*)d_in[6];
    const float* proj_b = (const float*)d_in[7];
    const float* ln2_w  = (const float*)d_in[8];
    const float* ln2_b  = (const float*)d_in[9];
    const float* fc1_w  = (const float*)d_in[10];
    const float* fc1_b  = (const float*)d_in[11];
    const float* fc2_w  = (const float*)d_in[12];
    const float* fc2_b  = (const float*)d_in[13];
    float* out = (float*)d_out;

    float* t;
    __half *q16, *h16, *o16, *m16, *w16;
    cudaGetSymbolAddress((void**)&t,   g_t);
    cudaGetSymbolAddress((void**)&q16, g_q16);
    cudaGetSymbolAddress((void**)&h16, g_h16);
    cudaGetSymbolAddress((void**)&o16, g_o16);
    cudaGetSymbolAddress((void**)&m16, g_m16);
    cudaGetSymbolAddress((void**)&w16, g_w16);

    cudaFuncSetAttribute(gemm_h<1>, cudaFuncAttributeMaxDynamicSharedMemorySize, GBSMEM_B);
    cudaFuncSetAttribute(gemm_h<2>, cudaFuncAttributeMaxDynamicSharedMemorySize, GBSMEM_B);
    cudaFuncSetAttribute(gemm_h<3>, cudaFuncAttributeMaxDynamicSharedMemorySize, GBSMEM_B);

    cvtw<<<W_TOT / 256, 256>>>(qkv_w, proj_w, fc1_w, fc2_w, w16);
    conv_pos_kernel<<<BATCH * CDIM, 256>>>(x, pos_w, pos_b);
    ln_kernel<<<TTOK, 256>>>(t, ln1_w, ln1_b, h16);
    gemm_h<3><<<dim3(QKVDIM / 128, TTOK / 128), 256, GBSMEM_B>>>(
        h16, w16 + W_QKV, nullptr, nullptr, nullptr, q16, QKVDIM, CDIM);
    attn_h<<<dim3(25, BATCH * NHEAD), 128>>>(q16, o16);
    gemm_h<1><<<dim3(CDIM / 128, TTOK / 128), 256, GBSMEM_B>>>(
        o16, w16 + W_PROJ, proj_b, t, t, nullptr, CDIM, CDIM);
    ln_kernel<<<TTOK, 256>>>(t, ln2_w, ln2_b, h16);
    gemm_h<2><<<dim3(HID / 128, TTOK / 128), 256, GBSMEM_B>>>(
        h16, w16 + W_FC1, fc1_b, nullptr, nullptr, m16, HID, CDIM);
    gemm_h<1><<<dim3(CDIM / 128, TTOK / 128), 256, GBSMEM_B>>>(
        m16, w16 + W_FC2, fc2_b, t, t, nullptr, CDIM, HID);
    untok_kernel<<<dim3(TOK / 32, CDIM / 32, BATCH), dim3(32, 8)>>>(out);
}

// round 16
// speedup vs baseline: 1.0061x; 1.0061x over previous
#include <cuda_runtime.h>
#include <cuda_fp16.h>
#include <math.h>
#include <stdint.h>

#define TOK    1568
#define BATCH  4
#define CDIM   768
#define TTOK   (BATCH*TOK)
#define QKVDIM 2304
#define HID    3072
#define NHEAD  12
#define DHEAD  64

#define W_QKV  0
#define W_PROJ 1769472
#define W_FC1  2359296
#define W_FC2  4718592
#define W_TOT  7077888

__device__ float  g_t[TTOK * CDIM];
__device__ __half g_q16[TTOK * QKVDIM];
__device__ __half g_h16[TTOK * CDIM];
__device__ __half g_o16[TTOK * CDIM];
__device__ __half g_m16[TTOK * HID];
__device__ __half g_w16[W_TOT];

// ---------------- ptx helpers ----------------
__device__ __forceinline__ void mma_f16(float* d, const uint32_t* a, const uint32_t* b) {
    asm volatile(
        "mma.sync.aligned.m16n8k16.row.col.f32.f16.f16.f32 "
        "{%0,%1,%2,%3}, {%4,%5,%6,%7}, {%8,%9}, {%0,%1,%2,%3};"
        : "+f"(d[0]), "+f"(d[1]), "+f"(d[2]), "+f"(d[3])
        : "r"(a[0]), "r"(a[1]), "r"(a[2]), "r"(a[3]), "r"(b[0]), "r"(b[1]));
}
__device__ __forceinline__ void ldsm4(uint32_t* r, uint32_t addr) {
    asm volatile("ldmatrix.sync.aligned.m8n8.x4.shared.b16 {%0,%1,%2,%3}, [%4];"
                 : "=r"(r[0]), "=r"(r[1]), "=r"(r[2]), "=r"(r[3]) : "r"(addr));
}
__device__ __forceinline__ void ldsm4t(uint32_t* r, uint32_t addr) {
    asm volatile("ldmatrix.sync.aligned.m8n8.x4.trans.shared.b16 {%0,%1,%2,%3}, [%4];"
                 : "=r"(r[0]), "=r"(r[1]), "=r"(r[2]), "=r"(r[3]) : "r"(addr));
}
__device__ __forceinline__ void cp16(uint32_t dst, const void* src) {
    asm volatile("cp.async.cg.shared.global [%0], [%1], 16;" :: "r"(dst), "l"(src));
}
__device__ __forceinline__ void cp_commit() { asm volatile("cp.async.commit_group;"); }
template <int N> __device__ __forceinline__ void cp_wait() {
    asm volatile("cp.async.wait_group %0;" :: "n"(N));
}
__device__ __forceinline__ float gelu_exact(float v) {
    return 0.5f * v * (1.f + erff(v * 0.70710678118654752f));
}

// ---------------- fused fp32 -> fp16 weight convert ----------------
__global__ void cvtw(const float* __restrict__ qkv_w, const float* __restrict__ proj_w,
                     const float* __restrict__ fc1_w, const float* __restrict__ fc2_w,
                     __half* __restrict__ dst) {
    int i = blockIdx.x * 256 + threadIdx.x;
    float v;
    if (i < W_PROJ)      v = qkv_w[i];
    else if (i < W_FC1)  v = proj_w[i - W_PROJ];
    else if (i < W_FC2)  v = fc1_w[i - W_FC1];
    else                 v = fc2_w[i - W_FC2];
    dst[i] = __float2half(v);
}

// ---------------- conv + bias + residual + tokenize ----------------
__global__ void conv_pos_kernel(const float* __restrict__ x,
                                const float* __restrict__ pw,
                                const float* __restrict__ pb) {
    int bc = blockIdx.x;
    int c  = bc % CDIM;
    int b  = bc / CDIM;
    __shared__ float sx[TOK];
    __shared__ float sw[27];
    int tid = threadIdx.x;
    const float* xs = x + (size_t)bc * TOK;
    for (int i = tid; i < TOK; i += 256) sx[i] = xs[i];
    if (tid < 27) sw[tid] = pw[c * 27 + tid];
    __syncthreads();
    float pbv = pb[c];
    for (int idx = tid; idx < TOK; idx += 256) {
        int d = idx / 196; int r = idx - d * 196;
        int h = r / 14;    int w = r - h * 14;
        float acc = 0.f;
        #pragma unroll
        for (int kd = 0; kd < 3; kd++) {
            int dd = d + kd - 1;
            if (dd < 0 || dd >= 8) continue;
            #pragma unroll
            for (int kh = 0; kh < 3; kh++) {
                int hh = h + kh - 1;
                if (hh < 0 || hh >= 14) continue;
                #pragma unroll
                for (int kw = 0; kw < 3; kw++) {
                    int ww = w + kw - 1;
                    if (ww < 0 || ww >= 14) continue;
                    acc += sw[kd * 9 + kh * 3 + kw] * sx[dd * 196 + hh * 14 + ww];
                }
            }
        }
        g_t[(size_t)(b * TOK + idx) * CDIM + c] = sx[idx] + acc + pbv;
    }
}

// ---------------- LayerNorm -> fp16 ----------------
__global__ void ln_kernel(const float* __restrict__ in, const float* __restrict__ w,
                          const float* __restrict__ bsrc, __half* __restrict__ out) {
    int t = blockIdx.x;
    int tid = threadIdx.x;
    const float* row = in + (size_t)t * CDIM;
    float v0 = row[tid], v1 = row[tid + 256], v2 = row[tid + 512];
    float s  = v0 + v1 + v2;
    float sq = v0 * v0 + v1 * v1 + v2 * v2;
    #pragma unroll
    for (int off = 16; off; off >>= 1) {
        s  += __shfl_xor_sync(0xffffffffu, s,  off);
        sq += __shfl_xor_sync(0xffffffffu, sq, off);
    }
    __shared__ float ss[8], ssq[8];
    int wid = tid >> 5, lid = tid & 31;
    if (lid == 0) { ss[wid] = s; ssq[wid] = sq; }
    __syncthreads();
    if (tid < 32) {
        s  = (lid < 8) ? ss[lid]  : 0.f;
        sq = (lid < 8) ? ssq[lid] : 0.f;
        #pragma unroll
        for (int off = 4; off; off >>= 1) {
            s  += __shfl_xor_sync(0xffffffffu, s,  off);
            sq += __shfl_xor_sync(0xffffffffu, sq, off);
        }
        if (lid == 0) { ss[0] = s; ssq[0] = sq; }
    }
    __syncthreads();
    float mean = ss[0] * (1.f / CDIM);
    float var  = ssq[0] * (1.f / CDIM) - mean * mean;
    float rs   = rsqrtf(var + 1e-5f);
    __half* orow = out + (size_t)t * CDIM;
    orow[tid]       = __float2half((v0 - mean) * rs * w[tid]       + bsrc[tid]);
    orow[tid + 256] = __float2half((v1 - mean) * rs * w[tid + 256] + bsrc[tid + 256]);
    orow[tid + 512] = __float2half((v2 - mean) * rs * w[tid + 512] + bsrc[tid + 512]);
}

// ---------------- fp16 mma GEMM (R13 winner: BK=32, 4-stage, ldmatrix) ----------------
#define GH_STRIDE 20
#define GH_MATW   (128 * GH_STRIDE)
#define GH_STAGEW (2 * GH_MATW)
#define GHSMEM_B  (4 * GH_STAGEW * 4)   // 81920 bytes

template <int MODE>   // 1: Cf=acc+bias+resid ; 2: Ch=gelu(acc+bias) ; 3: Ch=acc
__global__ void __launch_bounds__(256, 2)
gemm_h(const __half* __restrict__ A, const __half* __restrict__ B,
       const float* __restrict__ bias, const float* __restrict__ resid,
       float* __restrict__ Cf, __half* __restrict__ Ch, int N, int K) {
    extern __shared__ __align__(16) uint32_t smw[];
    int tid = threadIdx.x;
    int lane = tid & 31, warp = tid >> 5;
    int wm = warp >> 2, wn = warp & 3;
    int m0 = blockIdx.y << 7, n0 = blockIdx.x << 7;
    uint32_t smbase = (uint32_t)__cvta_generic_to_shared(smw);

    int lrow = tid >> 1;
    int lpart = tid & 1;
    const __half* Ag = A + (size_t)(m0 + lrow) * K + lpart * 16;
    const __half* Bg = B + (size_t)(n0 + lrow) * K + lpart * 16;
    uint32_t sa0 = smbase + (lrow * GH_STRIDE + lpart * 8) * 4;
    uint32_t sb0 = sa0 + GH_MATW * 4;

    int nch = K >> 5;
    auto load_chunk = [&](int ch) {
        uint32_t d = (uint32_t)(ch & 3) * (GH_STAGEW * 4);
        int off = ch << 5;
        cp16(sa0 + d, Ag + off); cp16(sa0 + d + 16, Ag + off + 8);
        cp16(sb0 + d, Bg + off); cp16(sb0 + d + 16, Bg + off + 8);
        cp_commit();
    };

    float acc[4][4][4];
    #pragma unroll
    for (int mi = 0; mi < 4; mi++)
        #pragma unroll
        for (int ni = 0; ni < 4; ni++)
            #pragma unroll
            for (int r = 0; r < 4; r++) acc[mi][ni][r] = 0.f;

    int grp = lane >> 3, trow = lane & 7;
    int arow = ((grp & 1) << 3) + trow, acol = (grp >> 1) << 3;
    int brow = ((grp >> 1) << 3) + trow, bcol = (grp & 1) << 3;
    uint32_t aaddr[4], baddr[2];
    #pragma unroll
    for (int mi = 0; mi < 4; mi++)
        aaddr[mi] = smbase + ((wm * 64 + mi * 16 + arow) * 40 + acol) * 2;
    #pragma unroll
    for (int np = 0; np < 2; np++)
        baddr[np] = smbase + GH_MATW * 4 + ((wn * 32 + np * 16 + brow) * 40 + bcol) * 2;

    load_chunk(0);
    load_chunk(1);
    load_chunk(2);
    for (int ch = 0; ch < nch; ch++) {
        if (ch + 3 <= nch - 1)      cp_wait<2>();
        else if (ch + 2 <= nch - 1) cp_wait<1>();
        else                        cp_wait<0>();
        __syncthreads();
        if (ch + 3 < nch) load_chunk(ch + 3);
        uint32_t soff = (uint32_t)(ch & 3) * (GH_STAGEW * 4);
        #pragma unroll
        for (int kt = 0; kt < 2; kt++) {
            uint32_t koff = soff + kt * 32;
            uint32_t af[4][4], bfr[2][4];
            #pragma unroll
            for (int mi = 0; mi < 4; mi++) ldsm4(af[mi], aaddr[mi] + koff);
            #pragma unroll
            for (int np = 0; np < 2; np++) ldsm4(bfr[np], baddr[np] + koff);
            #pragma unroll
            for (int mi = 0; mi < 4; mi++)
                #pragma unroll
                for (int ni = 0; ni < 4; ni++)
                    mma_f16(acc[mi][ni], af[mi], &bfr[ni >> 1][(ni & 1) * 2]);
        }
    }

    int r0 = lane >> 2, cq = (lane & 3) * 2;
    #pragma unroll
    for (int mi = 0; mi < 4; mi++) {
        int rowA = m0 + wm * 64 + mi * 16 + r0;
        int rowB = rowA + 8;
        #pragma unroll
        for (int ni = 0; ni < 4; ni++) {
            int col = n0 + wn * 32 + ni * 8 + cq;
            float2 va = make_float2(acc[mi][ni][0], acc[mi][ni][1]);
            float2 vb = make_float2(acc[mi][ni][2], acc[mi][ni][3]);
            if (MODE == 1) {
                float2 bv = *(const float2*)(bias + col);
                float2 ra = *(const float2*)(resid + (size_t)rowA * N + col);
                float2 rb = *(const float2*)(resid + (size_t)rowB * N + col);
                va.x += bv.x + ra.x; va.y += bv.y + ra.y;
                vb.x += bv.x + rb.x; vb.y += bv.y + rb.y;
                *(float2*)(Cf + (size_t)rowA * N + col) = va;
                *(float2*)(Cf + (size_t)rowB * N + col) = vb;
            } else if (MODE == 2) {
                float2 bv = *(const float2*)(bias + col);
                va.x = gelu_exact(va.x + bv.x); va.y = gelu_exact(va.y + bv.y);
                vb.x = gelu_exact(vb.x + bv.x); vb.y = gelu_exact(vb.y + bv.y);
                *(__half2*)(Ch + (size_t)rowA * N + col) = __floats2half2_rn(va.x, va.y);
                *(__half2*)(Ch + (size_t)rowB * N + col) = __floats2half2_rn(vb.x, vb.y);
            } else {
                *(__half2*)(Ch + (size_t)rowA * N + col) = __floats2half2_rn(va.x, va.y);
                *(__half2*)(Ch + (size_t)rowB * N + col) = __floats2half2_rn(vb.x, vb.y);
            }
        }
    }
}

// ---------------- fp16 flash attention: 128-query blocks, 256 thr, dynamic smem ----------------
#define A_KVBUF  (64 * 72 * 2)                     // 9216 B per K or V buffer
#define A_PSOFF  (4 * A_KVBUF)                     // after K[2], V[2]
#define ASMEM_B  (A_PSOFF + 128 * 72 * 2)          // 55296 bytes

__global__ void __launch_bounds__(256)
attn_h(const __half* __restrict__ qkv, __half* __restrict__ o) {
    extern __shared__ __align__(16) __half asm_h[];
    int tid = threadIdx.x, lane = tid & 31, warp = tid >> 5;   // 8 warps
    int bh = blockIdx.y;
    int b = bh / NHEAD, h = bh % NHEAD;
    int q0 = blockIdx.x * 128;
    const __half* base = qkv + (size_t)b * TOK * QKVDIM + h * DHEAD;

    int r0 = lane >> 2, kq = lane & 3;
    int qa = q0 + warp * 16 + r0;
    int qb = qa + 8;
    bool va = qa < TOK, vb = qb < TOK;

    uint32_t qf[4][4];
    {
        const __half2 sc = __floats2half2_rn(0.125f, 0.125f);
        int qca = va ? qa : TOK - 1;
        int qcb = vb ? qb : TOK - 1;
        const __half* pa = base + (size_t)qca * QKVDIM;
        const __half* pb = base + (size_t)qcb * QKVDIM;
        #pragma unroll
        for (int kt = 0; kt < 4; kt++) {
            int k = kt * 16 + 2 * kq;
            __half2 v;
            v = va ? __hmul2(*(const __half2*)(pa + k), sc) : __floats2half2_rn(0.f, 0.f);
            qf[kt][0] = *(uint32_t*)&v;
            v = vb ? __hmul2(*(const __half2*)(pb + k), sc) : __floats2half2_rn(0.f, 0.f);
            qf[kt][1] = *(uint32_t*)&v;
            v = va ? __hmul2(*(const __half2*)(pa + k + 8), sc) : __floats2half2_rn(0.f, 0.f);
            qf[kt][2] = *(uint32_t*)&v;
            v = vb ? __hmul2(*(const __half2*)(pb + k + 8), sc) : __floats2half2_rn(0.f, 0.f);
            qf[kt][3] = *(uint32_t*)&v;
        }
    }

    uint32_t smb = (uint32_t)__cvta_generic_to_shared(asm_h);
    uint32_t ksm = smb;
    uint32_t vsm = smb + 2 * A_KVBUF;
    uint32_t psm = smb + A_PSOFF;
    __half* Ps = asm_h + A_PSOFF / 2;

    // loader: 256 thr, 2 rows each per matrix
    int ldrow = tid >> 3, ldc8 = (tid & 7) << 3;
    auto loadKV = [&](int kc, int st) {
        uint32_t kb = ksm + st * A_KVBUF;
        uint32_t vbuf = vsm + st * A_KVBUF;
        #pragma unroll
        for (int i = 0; i < 2; i++) {
            int row = ldrow + i * 32;
            int kg = kc * 64 + row;
            if (kg > TOK - 1) kg = TOK - 1;
            const __half* src = base + (size_t)kg * QKVDIM;
            uint32_t doff = (row * 72 + ldc8) * 2;
            cp16(kb + doff,   src + CDIM + ldc8);
            cp16(vbuf + doff, src + 2 * CDIM + ldc8);
        }
        cp_commit();
    };

    int grp = lane >> 3, trow = lane & 7;
    int arow = ((grp & 1) << 3) + trow, acol = (grp >> 1) << 3;
    int brow = ((grp >> 1) << 3) + trow, bcol = (grp & 1) << 3;
    int vrow = ((grp & 1) << 3) + trow,  vcol = (grp >> 1) << 3;
    uint32_t koff_[4], voff_[4], paddr;
    #pragma unroll
    for (int np = 0; np < 4; np++) {
        koff_[np] = ((np * 16 + brow) * 72 + bcol) * 2;
        voff_[np] = (vrow * 72 + np * 16 + vcol) * 2;
    }
    paddr = psm + ((warp * 16 + arow) * 72 + acol) * 2;

    float oacc[8][4];
    #pragma unroll
    for (int nt = 0; nt < 8; nt++)
        #pragma unroll
        for (int rr = 0; rr < 4; rr++) oacc[nt][rr] = 0.f;
    float mi0 = -1e30f, mi1 = -1e30f, li0 = 0.f, li1 = 0.f;
    int prow = warp * 16 + r0;

    loadKV(0, 0);
    for (int kc = 0; kc < 25; kc++) {
        cp_wait<0>();
        __syncthreads();
        if (kc + 1 < 25) loadKV(kc + 1, (kc + 1) & 1);
        uint32_t kb = ksm + (kc & 1) * A_KVBUF;
        uint32_t vbuf = vsm + (kc & 1) * A_KVBUF;

        float s[8][4];
        #pragma unroll
        for (int ni = 0; ni < 8; ni++)
            #pragma unroll
            for (int rr = 0; rr < 4; rr++) s[ni][rr] = 0.f;
        #pragma unroll
        for (int kt = 0; kt < 4; kt++) {
            uint32_t koff = kt * 32;
            #pragma unroll
            for (int np = 0; np < 4; np++) {
                uint32_t bb[4];
                ldsm4(bb, kb + koff_[np] + koff);
                mma_f16(s[2 * np],     qf[kt], bb);
                mma_f16(s[2 * np + 1], qf[kt], bb + 2);
            }
        }
        if (kc == 24) {
            #pragma unroll
            for (int ni = 0; ni < 8; ni++) {
                int c = kc * 64 + ni * 8 + kq * 2;
                if (c >= TOK)     { s[ni][0] = -1e30f; s[ni][2] = -1e30f; }
                if (c + 1 >= TOK) { s[ni][1] = -1e30f; s[ni][3] = -1e30f; }
            }
        }
        float mr0 = -1e30f, mr1 = -1e30f;
        #pragma unroll
        for (int ni = 0; ni < 8; ni++) {
            mr0 = fmaxf(mr0, fmaxf(s[ni][0], s[ni][1]));
            mr1 = fmaxf(mr1, fmaxf(s[ni][2], s[ni][3]));
        }
        mr0 = fmaxf(mr0, __shfl_xor_sync(0xffffffffu, mr0, 1));
        mr0 = fmaxf(mr0, __shfl_xor_sync(0xffffffffu, mr0, 2));
        mr1 = fmaxf(mr1, __shfl_xor_sync(0xffffffffu, mr1, 1));
        mr1 = fmaxf(mr1, __shfl_xor_sync(0xffffffffu, mr1, 2));
        float mn0 = fmaxf(mi0, mr0), mn1 = fmaxf(mi1, mr1);
        float a0 = __expf(mi0 - mn0), a1 = __expf(mi1 - mn1);
        float sum0 = 0.f, sum1 = 0.f;
        #pragma unroll
        for (int ni = 0; ni < 8; ni++) {
            s[ni][0] = __expf(s[ni][0] - mn0);
            s[ni][1] = __expf(s[ni][1] - mn0);
            s[ni][2] = __expf(s[ni][2] - mn1);
            s[ni][3] = __expf(s[ni][3] - mn1);
            sum0 += s[ni][0] + s[ni][1];
            sum1 += s[ni][2] + s[ni][3];
        }
        sum0 += __shfl_xor_sync(0xffffffffu, sum0, 1);
        sum0 += __shfl_xor_sync(0xffffffffu, sum0, 2);
        sum1 += __shfl_xor_sync(0xffffffffu, sum1, 1);
        sum1 += __shfl_xor_sync(0xffffffffu, sum1, 2);
        li0 = li0 * a0 + sum0; li1 = li1 * a1 + sum1;
        mi0 = mn0; mi1 = mn1;
        #pragma unroll
        for (int nt = 0; nt < 8; nt++) {
            oacc[nt][0] *= a0; oacc[nt][1] *= a0;
            oacc[nt][2] *= a1; oacc[nt][3] *= a1;
        }
        #pragma unroll
        for (int ni = 0; ni < 8; ni++) {
            int col = ni * 8 + kq * 2;
            *(__half2*)&Ps[prow * 72 + col]       = __floats2half2_rn(s[ni][0], s[ni][1]);
            *(__half2*)&Ps[(prow + 8) * 72 + col] = __floats2half2_rn(s[ni][2], s[ni][3]);
        }
        __syncwarp();
        #pragma unroll
        for (int kt = 0; kt < 4; kt++) {
            uint32_t pf[4];
            ldsm4(pf, paddr + kt * 32);
            uint32_t vko = kt * 16 * 72 * 2;
            #pragma unroll
            for (int np = 0; np < 4; np++) {
                uint32_t bb[4];
                ldsm4t(bb, vbuf + voff_[np] + vko);
                mma_f16(oacc[2 * np],     pf, bb);
                mma_f16(oacc[2 * np + 1], pf, bb + 2);
            }
        }
    }

    float inv0 = 1.f / li0, inv1 = 1.f / li1;
    #pragma unroll
    for (int nt = 0; nt < 8; nt++) {
        int col = h * DHEAD + nt * 8 + kq * 2;
        if (va)
            *(__half2*)(o + (size_t)(b * TOK + qa) * CDIM + col) =
                __floats2half2_rn(oacc[nt][0] * inv0, oacc[nt][1] * inv0);
        if (vb)
            *(__half2*)(o + (size_t)(b * TOK + qb) * CDIM + col) =
                __floats2half2_rn(oacc[nt][2] * inv1, oacc[nt][3] * inv1);
    }
}

// ---------------- untokenize ----------------
__global__ void untok_kernel(float* __restrict__ out) {
    __shared__ float tile[32][33];
    int b  = blockIdx.z;
    int s0 = blockIdx.x * 32;
    int c0 = blockIdx.y * 32;
    int tx = threadIdx.x, ty = threadIdx.y;
    #pragma unroll
    for (int r = ty; r < 32; r += 8)
        tile[r][tx] = g_t[(size_t)(b * TOK + s0 + r) * CDIM + c0 + tx];
    __syncthreads();
    #pragma unroll
    for (int r = ty; r < 32; r += 8)
        out[(size_t)(b * CDIM + c0 + r) * TOK + s0 + tx] = tile[tx][r];
}

// ---------------- launch ----------------
extern "C" void kernel_launch(void* const* d_in, const int* in_sizes, int n_in,
                              void* d_out, int out_size) {
    const float* x      = (const float*)d_in[0];
    const float* pos_w  = (const float*)d_in[1];
    const float* pos_b  = (const float*)d_in[2];
    const float* ln1_w  = (const float*)d_in[3];
    const float* ln1_b  = (const float*)d_in[4];
    const float* qkv_w  = (const float*)d_in[5];
    const float* proj_w = (const float*)d_in[6];
    const float* proj_b = (const float*)d_in[7];
    const float* ln2_w  = (const float*)d_in[8];
    const float* ln2_b  = (const float*)d_in[9];
    const float* fc1_w  = (const float*)d_in[10];
    const float* fc1_b  = (const float*)d_in[11];
    const float* fc2_w  = (const float*)d_in[12];
    const float* fc2_b  = (const float*)d_in[13];
    float* out = (float*)d_out;

    float* t;
    __half *q16, *h16, *o16, *m16, *w16;
    cudaGetSymbolAddress((void**)&t,   g_t);
    cudaGetSymbolAddress((void**)&q16, g_q16);
    cudaGetSymbolAddress((void**)&h16, g_h16);
    cudaGetSymbolAddress((void**)&o16, g_o16);
    cudaGetSymbolAddress((void**)&m16, g_m16);
    cudaGetSymbolAddress((void**)&w16, g_w16);

    cudaFuncSetAttribute(gemm_h<1>, cudaFuncAttributeMaxDynamicSharedMemorySize, GHSMEM_B);
    cudaFuncSetAttribute(gemm_h<2>, cudaFuncAttributeMaxDynamicSharedMemorySize, GHSMEM_B);
    cudaFuncSetAttribute(gemm_h<3>, cudaFuncAttributeMaxDynamicSharedMemorySize, GHSMEM_B);
    cudaFuncSetAttribute(attn_h,    cudaFuncAttributeMaxDynamicSharedMemorySize, ASMEM_B);

    cvtw<<<W_TOT / 256, 256>>>(qkv_w, proj_w, fc1_w, fc2_w, w16);
    conv_pos_kernel<<<BATCH * CDIM, 256>>>(x, pos_w, pos_b);
    ln_kernel<<<TTOK, 256>>>(t, ln1_w, ln1_b, h16);
    gemm_h<3><<<dim3(QKVDIM / 128, TTOK / 128), 256, GHSMEM_B>>>(
        h16, w16 + W_QKV, nullptr, nullptr, nullptr, q16, QKVDIM, CDIM);
    attn_h<<<dim3(13, BATCH * NHEAD), 256, ASMEM_B>>>(q16, o16);
    gemm_h<1><<<dim3(CDIM / 128, TTOK / 128), 256, GHSMEM_B>>>(
        o16, w16 + W_PROJ, proj_b, t, t, nullptr, CDIM, CDIM);
    ln_kernel<<<TTOK, 256>>>(t, ln2_w, ln2_b, h16);
    gemm_h<2><<<dim3(HID / 128, TTOK / 128), 256, GHSMEM_B>>>(
        h16, w16 + W_FC1, fc1_b, nullptr, nullptr, m16, HID, CDIM);
    gemm_h<1><<<dim3(CDIM / 128, TTOK / 128), 256, GHSMEM_B>>>(
        m16, w16 + W_FC2, fc2_b, t, t, nullptr, CDIM, HID);
    untok_kernel<<<dim3(TOK / 32, CDIM / 32, BATCH), dim3(32, 8)>>>(out);
}

// round 17
// speedup vs baseline: 1.0636x; 1.0572x over previous
#include <cuda_runtime.h>
#include <cuda_fp16.h>
#include <math.h>
#include <stdint.h>

#define TOK    1568
#define BATCH  4
#define CDIM   768
#define TTOK   (BATCH*TOK)
#define QKVDIM 2304
#define HID    3072
#define NHEAD  12
#define DHEAD  64

#define W_QKV  0
#define W_PROJ 1769472
#define W_FC1  2359296
#define W_FC2  4718592
#define W_TOT  7077888

__device__ float  g_t[TTOK * CDIM];
__device__ __half g_q16[TTOK * QKVDIM];
__device__ __half g_h16[TTOK * CDIM];
__device__ __half g_o16[TTOK * CDIM];
__device__ __half g_m16[TTOK * HID];
__device__ __half g_w16[W_TOT];

// ---------------- ptx helpers ----------------
__device__ __forceinline__ void mma_f16(float* d, const uint32_t* a, const uint32_t* b) {
    asm volatile(
        "mma.sync.aligned.m16n8k16.row.col.f32.f16.f16.f32 "
        "{%0,%1,%2,%3}, {%4,%5,%6,%7}, {%8,%9}, {%0,%1,%2,%3};"
        : "+f"(d[0]), "+f"(d[1]), "+f"(d[2]), "+f"(d[3])
        : "r"(a[0]), "r"(a[1]), "r"(a[2]), "r"(a[3]), "r"(b[0]), "r"(b[1]));
}
__device__ __forceinline__ void ldsm4(uint32_t* r, uint32_t addr) {
    asm volatile("ldmatrix.sync.aligned.m8n8.x4.shared.b16 {%0,%1,%2,%3}, [%4];"
                 : "=r"(r[0]), "=r"(r[1]), "=r"(r[2]), "=r"(r[3]) : "r"(addr));
}
__device__ __forceinline__ void ldsm4t(uint32_t* r, uint32_t addr) {
    asm volatile("ldmatrix.sync.aligned.m8n8.x4.trans.shared.b16 {%0,%1,%2,%3}, [%4];"
                 : "=r"(r[0]), "=r"(r[1]), "=r"(r[2]), "=r"(r[3]) : "r"(addr));
}
__device__ __forceinline__ void cp16(uint32_t dst, const void* src) {
    asm volatile("cp.async.cg.shared.global [%0], [%1], 16;" :: "r"(dst), "l"(src));
}
__device__ __forceinline__ void cp_commit() { asm volatile("cp.async.commit_group;"); }
template <int N> __device__ __forceinline__ void cp_wait() {
    asm volatile("cp.async.wait_group %0;" :: "n"(N));
}
__device__ __forceinline__ float gelu_exact(float v) {
    return 0.5f * v * (1.f + erff(v * 0.70710678118654752f));
}

// ---------------- fused fp32 -> fp16 weight convert ----------------
__global__ void cvtw(const float* __restrict__ qkv_w, const float* __restrict__ proj_w,
                     const float* __restrict__ fc1_w, const float* __restrict__ fc2_w,
                     __half* __restrict__ dst) {
    int i = blockIdx.x * 256 + threadIdx.x;
    float v;
    if (i < W_PROJ)      v = qkv_w[i];
    else if (i < W_FC1)  v = proj_w[i - W_PROJ];
    else if (i < W_FC2)  v = fc1_w[i - W_FC1];
    else                 v = fc2_w[i - W_FC2];
    dst[i] = __float2half(v);
}

// ---------------- conv + bias + residual + tokenize ----------------
__global__ void conv_pos_kernel(const float* __restrict__ x,
                                const float* __restrict__ pw,
                                const float* __restrict__ pb) {
    int bc = blockIdx.x;
    int c  = bc % CDIM;
    int b  = bc / CDIM;
    __shared__ float sx[TOK];
    __shared__ float sw[27];
    int tid = threadIdx.x;
    const float* xs = x + (size_t)bc * TOK;
    for (int i = tid; i < TOK; i += 256) sx[i] = xs[i];
    if (tid < 27) sw[tid] = pw[c * 27 + tid];
    __syncthreads();
    float pbv = pb[c];
    for (int idx = tid; idx < TOK; idx += 256) {
        int d = idx / 196; int r = idx - d * 196;
        int h = r / 14;    int w = r - h * 14;
        float acc = 0.f;
        #pragma unroll
        for (int kd = 0; kd < 3; kd++) {
            int dd = d + kd - 1;
            if (dd < 0 || dd >= 8) continue;
            #pragma unroll
            for (int kh = 0; kh < 3; kh++) {
                int hh = h + kh - 1;
                if (hh < 0 || hh >= 14) continue;
                #pragma unroll
                for (int kw = 0; kw < 3; kw++) {
                    int ww = w + kw - 1;
                    if (ww < 0 || ww >= 14) continue;
                    acc += sw[kd * 9 + kh * 3 + kw] * sx[dd * 196 + hh * 14 + ww];
                }
            }
        }
        g_t[(size_t)(b * TOK + idx) * CDIM + c] = sx[idx] + acc + pbv;
    }
}

// ---------------- LayerNorm -> fp16 ----------------
__global__ void ln_kernel(const float* __restrict__ in, const float* __restrict__ w,
                          const float* __restrict__ bsrc, __half* __restrict__ out) {
    int t = blockIdx.x;
    int tid = threadIdx.x;
    const float* row = in + (size_t)t * CDIM;
    float v0 = row[tid], v1 = row[tid + 256], v2 = row[tid + 512];
    float s  = v0 + v1 + v2;
    float sq = v0 * v0 + v1 * v1 + v2 * v2;
    #pragma unroll
    for (int off = 16; off; off >>= 1) {
        s  += __shfl_xor_sync(0xffffffffu, s,  off);
        sq += __shfl_xor_sync(0xffffffffu, sq, off);
    }
    __shared__ float ss[8], ssq[8];
    int wid = tid >> 5, lid = tid & 31;
    if (lid == 0) { ss[wid] = s; ssq[wid] = sq; }
    __syncthreads();
    if (tid < 32) {
        s  = (lid < 8) ? ss[lid]  : 0.f;
        sq = (lid < 8) ? ssq[lid] : 0.f;
        #pragma unroll
        for (int off = 4; off; off >>= 1) {
            s  += __shfl_xor_sync(0xffffffffu, s,  off);
            sq += __shfl_xor_sync(0xffffffffu, sq, off);
        }
        if (lid == 0) { ss[0] = s; ssq[0] = sq; }
    }
    __syncthreads();
    float mean = ss[0] * (1.f / CDIM);
    float var  = ssq[0] * (1.f / CDIM) - mean * mean;
    float rs   = rsqrtf(var + 1e-5f);
    __half* orow = out + (size_t)t * CDIM;
    orow[tid]       = __float2half((v0 - mean) * rs * w[tid]       + bsrc[tid]);
    orow[tid + 256] = __float2half((v1 - mean) * rs * w[tid + 256] + bsrc[tid + 256]);
    orow[tid + 512] = __float2half((v2 - mean) * rs * w[tid + 512] + bsrc[tid + 512]);
}

// ---------------- fp16 mma GEMM (R13: BK=32, 4-stage, ldmatrix) ----------------
// MODE 1: Cf=acc+bias+resid ; 2: Ch=gelu(acc+bias) ; 3: Ch=acc ;
// MODE 4: out[(b*C+col)*TOK+s] = acc+bias+resid   (fused untokenize)
#define GH_STRIDE 20
#define GH_MATW   (128 * GH_STRIDE)
#define GH_STAGEW (2 * GH_MATW)
#define GHSMEM_B  (4 * GH_STAGEW * 4)   // 81920 bytes

template <int MODE>
__global__ void __launch_bounds__(256, 2)
gemm_h(const __half* __restrict__ A, const __half* __restrict__ B,
       const float* __restrict__ bias, const float* __restrict__ resid,
       float* __restrict__ Cf, __half* __restrict__ Ch, int N, int K) {
    extern __shared__ __align__(16) uint32_t smw[];
    int tid = threadIdx.x;
    int lane = tid & 31, warp = tid >> 5;
    int wm = warp >> 2, wn = warp & 3;
    int m0 = blockIdx.y << 7, n0 = blockIdx.x << 7;
    uint32_t smbase = (uint32_t)__cvta_generic_to_shared(smw);

    int lrow = tid >> 1;
    int lpart = tid & 1;
    const __half* Ag = A + (size_t)(m0 + lrow) * K + lpart * 16;
    const __half* Bg = B + (size_t)(n0 + lrow) * K + lpart * 16;
    uint32_t sa0 = smbase + (lrow * GH_STRIDE + lpart * 8) * 4;
    uint32_t sb0 = sa0 + GH_MATW * 4;

    int nch = K >> 5;
    auto load_chunk = [&](int ch) {
        uint32_t d = (uint32_t)(ch & 3) * (GH_STAGEW * 4);
        int off = ch << 5;
        cp16(sa0 + d, Ag + off); cp16(sa0 + d + 16, Ag + off + 8);
        cp16(sb0 + d, Bg + off); cp16(sb0 + d + 16, Bg + off + 8);
        cp_commit();
    };

    float acc[4][4][4];
    #pragma unroll
    for (int mi = 0; mi < 4; mi++)
        #pragma unroll
        for (int ni = 0; ni < 4; ni++)
            #pragma unroll
            for (int r = 0; r < 4; r++) acc[mi][ni][r] = 0.f;

    int grp = lane >> 3, trow = lane & 7;
    int arow = ((grp & 1) << 3) + trow, acol = (grp >> 1) << 3;
    int brow = ((grp >> 1) << 3) + trow, bcol = (grp & 1) << 3;
    uint32_t aaddr[4], baddr[2];
    #pragma unroll
    for (int mi = 0; mi < 4; mi++)
        aaddr[mi] = smbase + ((wm * 64 + mi * 16 + arow) * 40 + acol) * 2;
    #pragma unroll
    for (int np = 0; np < 2; np++)
        baddr[np] = smbase + GH_MATW * 4 + ((wn * 32 + np * 16 + brow) * 40 + bcol) * 2;

    load_chunk(0);
    load_chunk(1);
    load_chunk(2);
    for (int ch = 0; ch < nch; ch++) {
        if (ch + 3 <= nch - 1)      cp_wait<2>();
        else if (ch + 2 <= nch - 1) cp_wait<1>();
        else                        cp_wait<0>();
        __syncthreads();
        if (ch + 3 < nch) load_chunk(ch + 3);
        uint32_t soff = (uint32_t)(ch & 3) * (GH_STAGEW * 4);
        #pragma unroll
        for (int kt = 0; kt < 2; kt++) {
            uint32_t koff = soff + kt * 32;
            uint32_t af[4][4], bfr[2][4];
            #pragma unroll
            for (int mi = 0; mi < 4; mi++) ldsm4(af[mi], aaddr[mi] + koff);
            #pragma unroll
            for (int np = 0; np < 2; np++) ldsm4(bfr[np], baddr[np] + koff);
            #pragma unroll
            for (int mi = 0; mi < 4; mi++)
                #pragma unroll
                for (int ni = 0; ni < 4; ni++)
                    mma_f16(acc[mi][ni], af[mi], &bfr[ni >> 1][(ni & 1) * 2]);
        }
    }

    int r0 = lane >> 2, cq = (lane & 3) * 2;
    #pragma unroll
    for (int mi = 0; mi < 4; mi++) {
        int rowA = m0 + wm * 64 + mi * 16 + r0;
        int rowB = rowA + 8;
        #pragma unroll
        for (int ni = 0; ni < 4; ni++) {
            int col = n0 + wn * 32 + ni * 8 + cq;
            float2 va = make_float2(acc[mi][ni][0], acc[mi][ni][1]);
            float2 vb = make_float2(acc[mi][ni][2], acc[mi][ni][3]);
            if (MODE == 1) {
                float2 bv = *(const float2*)(bias + col);
                float2 ra = *(const float2*)(resid + (size_t)rowA * N + col);
                float2 rb = *(const float2*)(resid + (size_t)rowB * N + col);
                va.x += bv.x + ra.x; va.y += bv.y + ra.y;
                vb.x += bv.x + rb.x; vb.y += bv.y + rb.y;
                *(float2*)(Cf + (size_t)rowA * N + col) = va;
                *(float2*)(Cf + (size_t)rowB * N + col) = vb;
            } else if (MODE == 2) {
                float2 bv = *(const float2*)(bias + col);
                va.x = gelu_exact(va.x + bv.x); va.y = gelu_exact(va.y + bv.y);
                vb.x = gelu_exact(vb.x + bv.x); vb.y = gelu_exact(vb.y + bv.y);
                *(__half2*)(Ch + (size_t)rowA * N + col) = __floats2half2_rn(va.x, va.y);
                *(__half2*)(Ch + (size_t)rowB * N + col) = __floats2half2_rn(vb.x, vb.y);
            } else if (MODE == 3) {
                *(__half2*)(Ch + (size_t)rowA * N + col) = __floats2half2_rn(va.x, va.y);
                *(__half2*)(Ch + (size_t)rowB * N + col) = __floats2half2_rn(vb.x, vb.y);
            } else {
                // MODE 4: fused residual + untokenize to [B, C, D, H, W]
                float2 bv = *(const float2*)(bias + col);
                float2 ra = *(const float2*)(resid + (size_t)rowA * N + col);
                float2 rb = *(const float2*)(resid + (size_t)rowB * N + col);
                va.x += bv.x + ra.x; va.y += bv.y + ra.y;
                vb.x += bv.x + rb.x; vb.y += bv.y + rb.y;
                int ba = rowA / TOK, sa = rowA - ba * TOK;
                int bb2 = rowB / TOK, sb2 = rowB - bb2 * TOK;
                Cf[((size_t)ba * CDIM + col) * TOK + sa]         = va.x;
                Cf[((size_t)ba * CDIM + col + 1) * TOK + sa]     = va.y;
                Cf[((size_t)bb2 * CDIM + col) * TOK + sb2]       = vb.x;
                Cf[((size_t)bb2 * CDIM + col + 1) * TOK + sb2]   = vb.y;
            }
        }
    }
}

// ---------------- fp16 flash attention (R13 winner, exact) ----------------
__global__ void __launch_bounds__(128)
attn_h(const __half* __restrict__ qkv, __half* __restrict__ o) {
    __shared__ __align__(16) __half Ks[2][64 * 72];
    __shared__ __align__(16) __half Vs[2][64 * 72];
    __shared__ __align__(16) __half Ps[64 * 72];
    int tid = threadIdx.x, lane = tid & 31, warp = tid >> 5;
    int bh = blockIdx.y;
    int b = bh / NHEAD, h = bh % NHEAD;
    int q0 = blockIdx.x * 64;
    const __half* base = qkv + (size_t)b * TOK * QKVDIM + h * DHEAD;

    int r0 = lane >> 2, kq = lane & 3;
    int qa = q0 + warp * 16 + r0;
    int qb = qa + 8;
    bool va = qa < TOK, vb = qb < TOK;

    uint32_t qf[4][4];
    {
        const __half2 sc = __floats2half2_rn(0.125f, 0.125f);
        const __half* pa = base + (size_t)qa * QKVDIM;
        const __half* pb = base + (size_t)qb * QKVDIM;
        #pragma unroll
        for (int kt = 0; kt < 4; kt++) {
            int k = kt * 16 + 2 * kq;
            __half2 v;
            v = va ? __hmul2(*(const __half2*)(pa + k), sc) : __floats2half2_rn(0.f, 0.f);
            qf[kt][0] = *(uint32_t*)&v;
            v = vb ? __hmul2(*(const __half2*)(pb + k), sc) : __floats2half2_rn(0.f, 0.f);
            qf[kt][1] = *(uint32_t*)&v;
            v = va ? __hmul2(*(const __half2*)(pa + k + 8), sc) : __floats2half2_rn(0.f, 0.f);
            qf[kt][2] = *(uint32_t*)&v;
            v = vb ? __hmul2(*(const __half2*)(pb + k + 8), sc) : __floats2half2_rn(0.f, 0.f);
            qf[kt][3] = *(uint32_t*)&v;
        }
    }

    uint32_t ksm = (uint32_t)__cvta_generic_to_shared(Ks);
    uint32_t vsm = (uint32_t)__cvta_generic_to_shared(Vs);
    uint32_t psm = (uint32_t)__cvta_generic_to_shared(Ps);
    const uint32_t KVBUF = 64 * 72 * 2;

    int ldrow = tid >> 3, ldc8 = (tid & 7) << 3;
    auto loadKV = [&](int kc, int st) {
        uint32_t kb = ksm + st * KVBUF;
        uint32_t vbuf = vsm + st * KVBUF;
        #pragma unroll
        for (int i = 0; i < 4; i++) {
            int row = ldrow + i * 16;
            int kg = kc * 64 + row;
            if (kg > TOK - 1) kg = TOK - 1;
            const __half* src = base + (size_t)kg * QKVDIM;
            uint32_t doff = (row * 72 + ldc8) * 2;
            cp16(kb + doff,   src + CDIM + ldc8);
            cp16(vbuf + doff, src + 2 * CDIM + ldc8);
        }
        cp_commit();
    };

    int grp = lane >> 3, trow = lane & 7;
    int arow = ((grp & 1) << 3) + trow, acol = (grp >> 1) << 3;
    int brow = ((grp >> 1) << 3) + trow, bcol = (grp & 1) << 3;
    int vrow = ((grp & 1) << 3) + trow,  vcol = (grp >> 1) << 3;
    uint32_t koff_[4], voff_[4], paddr;
    #pragma unroll
    for (int np = 0; np < 4; np++) {
        koff_[np] = ((np * 16 + brow) * 72 + bcol) * 2;
        voff_[np] = (vrow * 72 + np * 16 + vcol) * 2;
    }
    paddr = psm + ((warp * 16 + arow) * 72 + acol) * 2;

    float oacc[8][4];
    #pragma unroll
    for (int nt = 0; nt < 8; nt++)
        #pragma unroll
        for (int rr = 0; rr < 4; rr++) oacc[nt][rr] = 0.f;
    float mi0 = -1e30f, mi1 = -1e30f, li0 = 0.f, li1 = 0.f;
    int prow = warp * 16 + r0;

    loadKV(0, 0);
    for (int kc = 0; kc < 25; kc++) {
        cp_wait<0>();
        __syncthreads();
        if (kc + 1 < 25) loadKV(kc + 1, (kc + 1) & 1);
        uint32_t kb = ksm + (kc & 1) * KVBUF;
        uint32_t vbuf = vsm + (kc & 1) * KVBUF;

        float s[8][4];
        #pragma unroll
        for (int ni = 0; ni < 8; ni++)
            #pragma unroll
            for (int rr = 0; rr < 4; rr++) s[ni][rr] = 0.f;
        #pragma unroll
        for (int kt = 0; kt < 4; kt++) {
            uint32_t koff = kt * 32;
            #pragma unroll
            for (int np = 0; np < 4; np++) {
                uint32_t bb[4];
                ldsm4(bb, kb + koff_[np] + koff);
                mma_f16(s[2 * np],     qf[kt], bb);
                mma_f16(s[2 * np + 1], qf[kt], bb + 2);
            }
        }
        if (kc == 24) {
            #pragma unroll
            for (int ni = 0; ni < 8; ni++) {
                int c = kc * 64 + ni * 8 + kq * 2;
                if (c >= TOK)     { s[ni][0] = -1e30f; s[ni][2] = -1e30f; }
                if (c + 1 >= TOK) { s[ni][1] = -1e30f; s[ni][3] = -1e30f; }
            }
        }
        float mr0 = -1e30f, mr1 = -1e30f;
        #pragma unroll
        for (int ni = 0; ni < 8; ni++) {
            mr0 = fmaxf(mr0, fmaxf(s[ni][0], s[ni][1]));
            mr1 = fmaxf(mr1, fmaxf(s[ni][2], s[ni][3]));
        }
        mr0 = fmaxf(mr0, __shfl_xor_sync(0xffffffffu, mr0, 1));
        mr0 = fmaxf(mr0, __shfl_xor_sync(0xffffffffu, mr0, 2));
        mr1 = fmaxf(mr1, __shfl_xor_sync(0xffffffffu, mr1, 1));
        mr1 = fmaxf(mr1, __shfl_xor_sync(0xffffffffu, mr1, 2));
        float mn0 = fmaxf(mi0, mr0), mn1 = fmaxf(mi1, mr1);
        float a0 = __expf(mi0 - mn0), a1 = __expf(mi1 - mn1);
        float sum0 = 0.f, sum1 = 0.f;
        #pragma unroll
        for (int ni = 0; ni < 8; ni++) {
            s[ni][0] = __expf(s[ni][0] - mn0);
            s[ni][1] = __expf(s[ni][1] - mn0);
            s[ni][2] = __expf(s[ni][2] - mn1);
            s[ni][3] = __expf(s[ni][3] - mn1);
            sum0 += s[ni][0] + s[ni][1];
            sum1 += s[ni][2] + s[ni][3];
        }
        sum0 += __shfl_xor_sync(0xffffffffu, sum0, 1);
        sum0 += __shfl_xor_sync(0xffffffffu, sum0, 2);
        sum1 += __shfl_xor_sync(0xffffffffu, sum1, 1);
        sum1 += __shfl_xor_sync(0xffffffffu, sum1, 2);
        li0 = li0 * a0 + sum0; li1 = li1 * a1 + sum1;
        mi0 = mn0; mi1 = mn1;
        #pragma unroll
        for (int nt = 0; nt < 8; nt++) {
            oacc[nt][0] *= a0; oacc[nt][1] *= a0;
            oacc[nt][2] *= a1; oacc[nt][3] *= a1;
        }
        #pragma unroll
        for (int ni = 0; ni < 8; ni++) {
            int col = ni * 8 + kq * 2;
            *(__half2*)&Ps[prow * 72 + col]       = __floats2half2_rn(s[ni][0], s[ni][1]);
            *(__half2*)&Ps[(prow + 8) * 72 + col] = __floats2half2_rn(s[ni][2], s[ni][3]);
        }
        __syncwarp();
        #pragma unroll
        for (int kt = 0; kt < 4; kt++) {
            uint32_t pf[4];
            ldsm4(pf, paddr + kt * 32);
            uint32_t vko = kt * 16 * 72 * 2;
            #pragma unroll
            for (int np = 0; np < 4; np++) {
                uint32_t bb[4];
                ldsm4t(bb, vbuf + voff_[np] + vko);
                mma_f16(oacc[2 * np],     pf, bb);
                mma_f16(oacc[2 * np + 1], pf, bb + 2);
            }
        }
    }

    float inv0 = 1.f / li0, inv1 = 1.f / li1;
    #pragma unroll
    for (int nt = 0; nt < 8; nt++) {
        int col = h * DHEAD + nt * 8 + kq * 2;
        if (va)
            *(__half2*)(o + (size_t)(b * TOK + qa) * CDIM + col) =
                __floats2half2_rn(oacc[nt][0] * inv0, oacc[nt][1] * inv0);
        if (vb)
            *(__half2*)(o + (size_t)(b * TOK + qb) * CDIM + col) =
                __floats2half2_rn(oacc[nt][2] * inv1, oacc[nt][3] * inv1);
    }
}

// ---------------- launch ----------------
extern "C" void kernel_launch(void* const* d_in, const int* in_sizes, int n_in,
                              void* d_out, int out_size) {
    const float* x      = (const float*)d_in[0];
    const float* pos_w  = (const float*)d_in[1];
    const float* pos_b  = (const float*)d_in[2];
    const float* ln1_w  = (const float*)d_in[3];
    const float* ln1_b  = (const float*)d_in[4];
    const float* qkv_w  = (const float*)d_in[5];
    const float* proj_w = (const float*)d_in[6];
    const float* proj_b = (const float*)d_in[7];
    const float* ln2_w  = (const float*)d_in[8];
    const float* ln2_b  = (const float*)d_in[9];
    const float* fc1_w  = (const float*)d_in[10];
    const float* fc1_b  = (const float*)d_in[11];
    const float* fc2_w  = (const float*)d_in[12];
    const float* fc2_b  = (const float*)d_in[13];
    float* out = (float*)d_out;

    float* t;
    __half *q16, *h16, *o16, *m16, *w16;
    cudaGetSymbolAddress((void**)&t,   g_t);
    cudaGetSymbolAddress((void**)&q16, g_q16);
    cudaGetSymbolAddress((void**)&h16, g_h16);
    cudaGetSymbolAddress((void**)&o16, g_o16);
    cudaGetSymbolAddress((void**)&m16, g_m16);
    cudaGetSymbolAddress((void**)&w16, g_w16);

    cudaFuncSetAttribute(gemm_h<1>, cudaFuncAttributeMaxDynamicSharedMemorySize, GHSMEM_B);
    cudaFuncSetAttribute(gemm_h<2>, cudaFuncAttributeMaxDynamicSharedMemorySize, GHSMEM_B);
    cudaFuncSetAttribute(gemm_h<3>, cudaFuncAttributeMaxDynamicSharedMemorySize, GHSMEM_B);
    cudaFuncSetAttribute(gemm_h<4>, cudaFuncAttributeMaxDynamicSharedMemorySize, GHSMEM_B);

    cvtw<<<W_TOT / 256, 256>>>(qkv_w, proj_w, fc1_w, fc2_w, w16);
    conv_pos_kernel<<<BATCH * CDIM, 256>>>(x, pos_w, pos_b);
    ln_kernel<<<TTOK, 256>>>(t, ln1_w, ln1_b, h16);
    gemm_h<3><<<dim3(QKVDIM / 128, TTOK / 128), 256, GHSMEM_B>>>(
        h16, w16 + W_QKV, nullptr, nullptr, nullptr, q16, QKVDIM, CDIM);
    attn_h<<<dim3(25, BATCH * NHEAD), 128>>>(q16, o16);
    gemm_h<1><<<dim3(CDIM / 128, TTOK / 128), 256, GHSMEM_B>>>(
        o16, w16 + W_PROJ, proj_b, t, t, nullptr, CDIM, CDIM);
    ln_kernel<<<TTOK, 256>>>(t, ln2_w, ln2_b, h16);
    gemm_h<2><<<dim3(HID / 128, TTOK / 128), 256, GHSMEM_B>>>(
        h16, w16 + W_FC1, fc1_b, nullptr, nullptr, m16, HID, CDIM);
    // final GEMM: residual + fused untokenize straight into out
    gemm_h<4><<<dim3(CDIM / 128, TTOK / 128), 256, GHSMEM_B>>>(
        m16, w16 + W_FC2, fc2_b, t, out, nullptr, CDIM, HID);
}